// round 1
// baseline (speedup 1.0000x reference)
#include <cuda_runtime.h>

// ---------------------------------------------------------------------------
// Problem constants
//   B=16, H=W=1024, ROUTE=(512,256) -> ph=2, pw=4, L=8 patches, NPATCH=128
//   scale i: W_i = 1024>>i, kh_i = 512>>i, kw_i = 256>>i
//   out layout: [0]=loss, [1..16M]=out_img, [16M+1..32M]=lab_img
// ---------------------------------------------------------------------------

#define NPATCH 128
#define IMG0   16777216   // 16*1024*1024

__device__ double g_Sabs[4][NPATCH];
__device__ double g_Scnt[4][NPATCH];
__device__ double g_Ssq [4][NPATCH];
__device__ int    g_mask[NPATCH];

// ---------------------------------------------------------------------------
__global__ void k_init() {
    int t = threadIdx.x;                     // 512 threads, 4*128 = 512 slots
    ((double*)g_Sabs)[t] = 0.0;
    ((double*)g_Scnt)[t] = 0.0;
    ((double*)g_Ssq )[t] = 0.0;
}

// ---------------------------------------------------------------------------
// Per-patch reduction. One block handles a contiguous slice of one patch.
//   grid = NPATCH * bpp blocks, 256 threads, float4 per thread per iter.
//   bpp * iters * 1024 == kh*kw (patch elements)
__global__ void k_patch_reduce(const float* __restrict__ pre,
                               const float* __restrict__ gt,
                               int scale, int kwShift, int kh, int wShift,
                               int bpp, int iters)
{
    int patch = blockIdx.x / bpp;
    int slice = blockIdx.x - patch * bpp;
    int b  = patch >> 3;
    int l  = patch & 7;
    int pr = l >> 2;
    int pc = l & 3;
    int kwm1   = (1 << kwShift) - 1;
    int baseImg = b << (2 * wShift);         // b * W_i * W_i  (square images)
    int eBase = slice * (iters << 10) + (threadIdx.x << 2);

    float sabs = 0.f, scnt = 0.f, ssq = 0.f;

    for (int it = 0; it < iters; ++it) {
        int e  = eBase + (it << 10);
        int ly = e >> kwShift;
        int lx = e & kwm1;
        int gy = pr * kh + ly;
        int gx = (pc << kwShift) + lx;
        int idx = baseImg + (gy << wShift) + gx;
        float4 p = *(const float4*)(pre + idx);
        float4 g = *(const float4*)(gt  + idx);

        #define ACC(pp, gg) { float g2 = (gg) * 200.0f; float d = g2 - (pp);   \
                              if (g2 > 0.0f) { sabs += fabsf(d); scnt += 1.0f; } \
                              ssq += d * d; }
        ACC(p.x, g.x) ACC(p.y, g.y) ACC(p.z, g.z) ACC(p.w, g.w)
        #undef ACC
    }

    __shared__ double sA[256], sC[256], sQ[256];
    int tid = threadIdx.x;
    sA[tid] = (double)sabs;
    sC[tid] = (double)scnt;
    sQ[tid] = (double)ssq;
    __syncthreads();
    #pragma unroll
    for (int s = 128; s > 0; s >>= 1) {
        if (tid < s) {
            sA[tid] += sA[tid + s];
            sC[tid] += sC[tid + s];
            sQ[tid] += sQ[tid + s];
        }
        __syncthreads();
    }
    if (tid == 0) {
        atomicAdd(&g_Sabs[scale][patch], sA[0]);
        atomicAdd(&g_Scnt[scale][patch], sC[0]);
        atomicAdd(&g_Ssq [scale][patch], sQ[0]);
    }
}

// ---------------------------------------------------------------------------
// argmin over scales per patch + weighted loss. 1 block, 128 threads.
__global__ void k_select(float* __restrict__ out)
{
    int t = threadIdx.x;                     // patch id
    __shared__ double num[4];
    __shared__ int    cnt[4];
    if (t < 4) { num[t] = 0.0; cnt[t] = 0; }
    __syncthreads();

    double best = 1e300;
    int mi = 0;
    #pragma unroll
    for (int i = 0; i < 4; ++i) {
        double e = g_Sabs[i][t] / (g_Scnt[i][t] + (double)0.1f);
        if (e < best) { best = e; mi = i; }  // strict < keeps first-min (argmin)
    }
    g_mask[t] = mi;
    atomicAdd(&num[mi], g_Ssq[mi][t]);
    atomicAdd(&cnt[mi], 1);
    __syncthreads();

    if (t == 0) {
        const double w[4]  = {0.5, 0.25, 0.125, 0.0625};
        const double pe[4] = {131072.0, 32768.0, 8192.0, 2048.0};
        double loss = 0.0;
        #pragma unroll
        for (int i = 0; i < 4; ++i)
            loss += w[i] * (num[i] / ((double)cnt[i] * pe[i] + (double)0.01f));
        out[0] = (float)loss;
    }
}

// ---------------------------------------------------------------------------
// Compose out_img & lab_img. 4 pixels per thread (one X-aligned quad).
// pad_w values (0,64,96,112) and kw values are multiples of 4, so a quad is
// entirely inside or outside the inner region -> single branch, float4 reads.
__global__ void k_write(const float* __restrict__ p0, const float* __restrict__ p1,
                        const float* __restrict__ p2, const float* __restrict__ p3,
                        const float* __restrict__ g0, const float* __restrict__ g1,
                        const float* __restrict__ g2, const float* __restrict__ g3,
                        float* __restrict__ out)
{
    int q = blockIdx.x * blockDim.x + threadIdx.x;   // 4,194,304 threads
    int P = q << 2;                                   // pixel base
    int b = P >> 20;
    int r = P & 1048575;
    int Y = r >> 10;
    int X = r & 1023;
    int pr = Y >> 9;
    int pc = X >> 8;
    int mi = g_mask[(b << 3) | (pr << 2) | pc];

    int kh = 512 >> mi;
    int kw = 256 >> mi;
    int iy = (Y & 511) - ((512 - kh) >> 1);
    int ix = (X & 255) - ((256 - kw) >> 1);

    const float PADV = 0.2f / 200.0f;
    float o0 = PADV, o1 = PADV, o2 = PADV, o3 = PADV;
    float l0 = PADV, l1 = PADV, l2 = PADV, l3 = PADV;

    if ((unsigned)iy < (unsigned)kh && (unsigned)ix < (unsigned)kw) {
        int ws  = 10 - mi;                            // log2 W_i
        int idx = (b << (2 * ws)) + ((pr * kh + iy) << ws)
                + (pc << (8 - mi)) + ix;
        const float* pp = (mi == 0) ? p0 : (mi == 1) ? p1 : (mi == 2) ? p2 : p3;
        const float* gg = (mi == 0) ? g0 : (mi == 1) ? g1 : (mi == 2) ? g2 : g3;
        float4 p = *(const float4*)(pp + idx);
        float4 g = *(const float4*)(gg + idx);
        o0 = p.x / 200.0f; o1 = p.y / 200.0f; o2 = p.z / 200.0f; o3 = p.w / 200.0f;
        l0 = (g.x * 200.0f) / 200.0f;
        l1 = (g.y * 200.0f) / 200.0f;
        l2 = (g.z * 200.0f) / 200.0f;
        l3 = (g.w * 200.0f) / 200.0f;
    }

    float* ob = out + 1;
    float* lb = out + 1 + IMG0;
    ob[P]     = o0; ob[P + 1] = o1; ob[P + 2] = o2; ob[P + 3] = o3;
    lb[P]     = l0; lb[P + 1] = l1; lb[P + 2] = l2; lb[P + 3] = l3;
}

// ---------------------------------------------------------------------------
extern "C" void kernel_launch(void* const* d_in, const int* in_sizes, int n_in,
                              void* d_out, int out_size)
{
    const float *pre[4], *gt[4];
    // setup_inputs dict order is interleaved (pre0,gt0,pre1,gt1,...); detect
    // grouped order (pre0..pre3,gt0..gt3) defensively via sizes.
    if (n_in >= 8 && in_sizes[1] == in_sizes[0]) {
        for (int i = 0; i < 4; ++i) {
            pre[i] = (const float*)d_in[2 * i];
            gt [i] = (const float*)d_in[2 * i + 1];
        }
    } else {
        for (int i = 0; i < 4; ++i) {
            pre[i] = (const float*)d_in[i];
            gt [i] = (const float*)d_in[4 + i];
        }
    }
    float* out = (float*)d_out;

    k_init<<<1, 512>>>();
    // scale, kwShift, kh, wShift, bpp, iters   (bpp*iters*1024 == kh*kw)
    k_patch_reduce<<<NPATCH * 16, 256>>>(pre[0], gt[0], 0, 8, 512, 10, 16, 8);
    k_patch_reduce<<<NPATCH *  4, 256>>>(pre[1], gt[1], 1, 7, 256,  9,  4, 8);
    k_patch_reduce<<<NPATCH *  1, 256>>>(pre[2], gt[2], 2, 6, 128,  8,  1, 8);
    k_patch_reduce<<<NPATCH *  1, 256>>>(pre[3], gt[3], 3, 5,  64,  7,  1, 2);
    k_select<<<1, 128>>>(out);
    k_write<<<16384, 256>>>(pre[0], pre[1], pre[2], pre[3],
                            gt[0], gt[1], gt[2], gt[3], out);
    (void)out_size;
}

// round 2
// speedup vs baseline: 1.0704x; 1.0704x over previous
#include <cuda_runtime.h>

// ---------------------------------------------------------------------------
// B=16, H=W=1024, ROUTE=(512,256) -> ph=2, pw=4, L=8, NPATCH=128
// scale i: W_i=1024>>i, kh=512>>i, kw=256>>i
// out: [0]=loss, [1..16M]=out_img, [16M+1..32M]=lab_img
// ---------------------------------------------------------------------------

#define NPATCH 128
#define IMG0   16777216
#define NSLOTS 5632   // 4096 + 1024 + 256 + 256 partial slots

__device__ double g_pA[NSLOTS];
__device__ double g_pC[NSLOTS];
__device__ double g_pQ[NSLOTS];
__device__ int    g_mask[NPATCH];

// ---------------------------------------------------------------------------
// Fused per-patch reduction over all 4 scales in one launch.
//   scale0: blocks [0,4096)    32/patch, iters=4
//   scale1: blocks [4096,5120)  8/patch, iters=4
//   scale2: blocks [5120,5376)  2/patch, iters=4
//   scale3: blocks [5376,5632)  2/patch, iters=1
// Each block-iter covers 1024 float4-quads read as float4.
__global__ void k_reduce(const float* __restrict__ p0, const float* __restrict__ p1,
                         const float* __restrict__ p2, const float* __restrict__ p3,
                         const float* __restrict__ g0, const float* __restrict__ g1,
                         const float* __restrict__ g2, const float* __restrict__ g3)
{
    int bid = blockIdx.x;
    int scale, base;
    if      (bid < 4096) { scale = 0; base = 0;    }
    else if (bid < 5120) { scale = 1; base = 4096; }
    else if (bid < 5376) { scale = 2; base = 5120; }
    else                 { scale = 3; base = 5376; }
    int rel = bid - base;

    const int kwS_t[4]  = {8, 7, 6, 5};
    const int kh_t[4]   = {512, 256, 128, 64};
    const int wS_t[4]   = {10, 9, 8, 7};
    const int bpp_t[4]  = {32, 8, 2, 2};
    const int it_t[4]   = {4, 4, 4, 1};

    int kwShift = kwS_t[scale];
    int kh      = kh_t[scale];
    int wShift  = wS_t[scale];
    int bpp     = bpp_t[scale];
    int iters   = it_t[scale];

    const float* pre = (scale == 0) ? p0 : (scale == 1) ? p1 : (scale == 2) ? p2 : p3;
    const float* gt  = (scale == 0) ? g0 : (scale == 1) ? g1 : (scale == 2) ? g2 : g3;

    int patch = rel / bpp;
    int slice = rel - patch * bpp;
    int b  = patch >> 3;
    int l  = patch & 7;
    int pr = l >> 2;
    int pc = l & 3;
    int kwm1    = (1 << kwShift) - 1;
    int baseImg = b << (2 * wShift);
    int eBase   = slice * (iters << 10) + (threadIdx.x << 2);

    float sabs = 0.f, scnt = 0.f, ssq = 0.f;

    #pragma unroll 4
    for (int it = 0; it < iters; ++it) {
        int e  = eBase + (it << 10);
        int ly = e >> kwShift;
        int lx = e & kwm1;
        int gy = pr * kh + ly;
        int gx = (pc << kwShift) + lx;
        int idx = baseImg + (gy << wShift) + gx;
        float4 p = *(const float4*)(pre + idx);
        float4 g = *(const float4*)(gt  + idx);

        #define ACC(pp, gg) { float g2 = (gg) * 200.0f; float d = g2 - (pp);     \
                              if (g2 > 0.0f) { sabs += fabsf(d); scnt += 1.0f; } \
                              ssq += d * d; }
        ACC(p.x, g.x) ACC(p.y, g.y) ACC(p.z, g.z) ACC(p.w, g.w)
        #undef ACC
    }

    __shared__ double sA[256], sC[256], sQ[256];
    int tid = threadIdx.x;
    sA[tid] = (double)sabs;
    sC[tid] = (double)scnt;
    sQ[tid] = (double)ssq;
    __syncthreads();
    #pragma unroll
    for (int s = 128; s > 0; s >>= 1) {
        if (tid < s) {
            sA[tid] += sA[tid + s];
            sC[tid] += sC[tid + s];
            sQ[tid] += sQ[tid + s];
        }
        __syncthreads();
    }
    if (tid == 0) {
        g_pA[bid] = sA[0];
        g_pC[bid] = sC[0];
        g_pQ[bid] = sQ[0];
    }
}

// ---------------------------------------------------------------------------
// Per-patch argmin + weighted loss. 1 block, 128 threads (one per patch).
__global__ void k_select(float* __restrict__ out)
{
    int t = threadIdx.x;
    __shared__ double num[4];
    __shared__ int    cnt[4];
    if (t < 4) { num[t] = 0.0; cnt[t] = 0; }
    __syncthreads();

    const int base4[4] = {0, 4096, 5120, 5376};
    const int cnt4[4]  = {32, 8, 2, 2};

    double best = 1e300;
    int mi = 0;
    double ssqs[4];
    #pragma unroll
    for (int i = 0; i < 4; ++i) {
        double A = 0.0, C = 0.0, Q = 0.0;
        int s0 = base4[i] + t * cnt4[i];
        for (int s = 0; s < cnt4[i]; ++s) {
            A += g_pA[s0 + s];
            C += g_pC[s0 + s];
            Q += g_pQ[s0 + s];
        }
        ssqs[i] = Q;
        double e = A / (C + (double)0.1f);
        if (e < best) { best = e; mi = i; }   // strict < = first-min (argmin)
    }
    g_mask[t] = mi;
    atomicAdd(&num[mi], ssqs[mi]);
    atomicAdd(&cnt[mi], 1);
    __syncthreads();

    if (t == 0) {
        const double w[4]  = {0.5, 0.25, 0.125, 0.0625};
        const double pe[4] = {131072.0, 32768.0, 8192.0, 2048.0};
        double loss = 0.0;
        #pragma unroll
        for (int i = 0; i < 4; ++i)
            loss += w[i] * (num[i] / ((double)cnt[i] * pe[i] + (double)0.01f));
        out[0] = (float)loss;
    }
}

// ---------------------------------------------------------------------------
// Compose out_img & lab_img. One block = one 1024-pixel row. Values are
// computed into smem (float4 gather reads), then emitted with ALIGNED
// float4 stores despite the +1 global offset (255 STG.128 + 4 edge scalars
// per array per block).
__global__ void k_write(const float* __restrict__ p0, const float* __restrict__ p1,
                        const float* __restrict__ p2, const float* __restrict__ p3,
                        const float* __restrict__ g0, const float* __restrict__ g1,
                        const float* __restrict__ g2, const float* __restrict__ g3,
                        float* __restrict__ out)
{
    __shared__ float so[1024];
    __shared__ float sl[1024];

    int t    = threadIdx.x;
    int base = blockIdx.x << 10;          // pixel base (one full image row)
    int P    = base + (t << 2);
    int b  = P >> 20;
    int r  = P & 1048575;
    int Y  = r >> 10;
    int X  = r & 1023;
    int pr = Y >> 9;
    int pc = X >> 8;
    int mi = g_mask[(b << 3) | (pr << 2) | pc];

    int kh = 512 >> mi;
    int kw = 256 >> mi;
    int iy = (Y & 511) - ((512 - kh) >> 1);
    int ix = (X & 255) - ((256 - kw) >> 1);

    const float PADV = 0.2f / 200.0f;
    float4 vo = make_float4(PADV, PADV, PADV, PADV);
    float4 vl = vo;

    if ((unsigned)iy < (unsigned)kh && (unsigned)ix < (unsigned)kw) {
        int ws  = 10 - mi;
        int idx = (b << (2 * ws)) + ((pr * kh + iy) << ws)
                + (pc << (8 - mi)) + ix;
        const float* pp = (mi == 0) ? p0 : (mi == 1) ? p1 : (mi == 2) ? p2 : p3;
        const float* gg = (mi == 0) ? g0 : (mi == 1) ? g1 : (mi == 2) ? g2 : g3;
        float4 p = *(const float4*)(pp + idx);
        float4 g = *(const float4*)(gg + idx);
        vo = make_float4(p.x / 200.0f, p.y / 200.0f, p.z / 200.0f, p.w / 200.0f);
        vl = make_float4((g.x * 200.0f) / 200.0f, (g.y * 200.0f) / 200.0f,
                         (g.z * 200.0f) / 200.0f, (g.w * 200.0f) / 200.0f);
    }

    *(float4*)(so + (t << 2)) = vo;
    *(float4*)(sl + (t << 2)) = vl;
    __syncthreads();

    float* ob = out + 1 + base;           // ob is 4-byte-aligned +4 mod 16
    float* lb = ob + IMG0;                // IMG0 % 4 == 0 -> same phase

    if (t < 255) {
        int k = 3 + (t << 2);             // (1+base+k) % 4 == 0 -> 16B aligned
        float4 a = make_float4(so[k], so[k + 1], so[k + 2], so[k + 3]);
        float4 c = make_float4(sl[k], sl[k + 1], sl[k + 2], sl[k + 3]);
        __stcs((float4*)(ob + k), a);
        __stcs((float4*)(lb + k), c);
    } else {
        ob[0] = so[0]; ob[1] = so[1]; ob[2] = so[2]; ob[1023] = so[1023];
        lb[0] = sl[0]; lb[1] = sl[1]; lb[2] = sl[2]; lb[1023] = sl[1023];
    }
}

// ---------------------------------------------------------------------------
extern "C" void kernel_launch(void* const* d_in, const int* in_sizes, int n_in,
                              void* d_out, int out_size)
{
    const float *pre[4], *gt[4];
    if (n_in >= 8 && in_sizes[1] == in_sizes[0]) {        // interleaved
        for (int i = 0; i < 4; ++i) {
            pre[i] = (const float*)d_in[2 * i];
            gt [i] = (const float*)d_in[2 * i + 1];
        }
    } else {                                              // grouped
        for (int i = 0; i < 4; ++i) {
            pre[i] = (const float*)d_in[i];
            gt [i] = (const float*)d_in[4 + i];
        }
    }
    float* out = (float*)d_out;

    k_reduce<<<NSLOTS, 256>>>(pre[0], pre[1], pre[2], pre[3],
                              gt[0], gt[1], gt[2], gt[3]);
    k_select<<<1, 128>>>(out);
    k_write<<<16384, 256>>>(pre[0], pre[1], pre[2], pre[3],
                            gt[0], gt[1], gt[2], gt[3], out);
    (void)out_size;
}